// round 4
// baseline (speedup 1.0000x reference)
#include <cuda_runtime.h>
#include <cuda_bf16.h>
#include <cuda_fp16.h>
#include <math.h>

#define N_IN   12288
#define H0     256
#define BATCH  8192
#define WARPS_PER_BLOCK 8
#define GRID   512               // 512 blocks * 8 warps * 2 rows = 8192

// Scratch (static device allocations are allowed)
__device__ __half g_ft_wt_h[N_IN * H0];   // (12288, 256) transposed, fp16
__device__ __half g_w1h[512 * 32];        // l1_w repacked: [i4][h][c] fp16
__device__ float  g_w2t[32 * 32];         // l2_w transposed [i][h2]
__device__ int    g_side_mode;            // 0=uint8, 1=int32, 2=float32

// ---------------------------------------------------------------------------
// Detect storage dtype of boolean 'side' by byte patterns (first 8192 bytes).
// ---------------------------------------------------------------------------
__global__ void side_mode_kernel(const unsigned char* __restrict__ p) {
    __shared__ int c3F, cOdd;
    if (threadIdx.x == 0) { c3F = 0; cOdd = 0; }
    __syncthreads();
    int l3f = 0, lodd = 0;
    for (int i = threadIdx.x; i < 8192; i += blockDim.x) {
        unsigned char b = p[i];
        if ((i & 3) == 3 && b == 0x3F) l3f++;
        if ((i & 3) != 0 && b != 0)    lodd++;
    }
    atomicAdd(&c3F, l3f);
    atomicAdd(&cOdd, lodd);
    __syncthreads();
    if (threadIdx.x == 0)
        g_side_mode = (c3F > 0) ? 2 : ((cOdd > 0) ? 0 : 1);
}

// ---------------------------------------------------------------------------
// Tiled transpose + fp16 convert: ft_w (256, 12288) -> g_ft_wt_h (12288, 256)
// ---------------------------------------------------------------------------
__global__ void transpose_ft_kernel(const float* __restrict__ ft_w) {
    __shared__ float tile[32][33];
    int f = blockIdx.x * 32 + threadIdx.x;
    int h = blockIdx.y * 32 + threadIdx.y;
    tile[threadIdx.y][threadIdx.x] = ft_w[h * N_IN + f];
    __syncthreads();
    int oh = blockIdx.y * 32 + threadIdx.x;
    int of = blockIdx.x * 32 + threadIdx.y;
    g_ft_wt_h[of * H0 + oh] = __float2half_rn(tile[threadIdx.x][threadIdx.y]);
}

// ---------------------------------------------------------------------------
// Repack tail weights: g_w1h[i4*128 + h*4 + c] = half(l1_w[h*512 + i4*4 + c])
//                      g_w2t[i*32 + h2]       = l2_w[h2*32 + i]
// ---------------------------------------------------------------------------
__global__ void prep_tail_kernel(const float* __restrict__ l1w,
                                 const float* __restrict__ l2w) {
    for (int idx = threadIdx.x; idx < 32 * 512; idx += blockDim.x) {
        int h = idx >> 9, i = idx & 511;
        int i4 = i >> 2, c = i & 3;
        g_w1h[i4 * 128 + h * 4 + c] = __float2half_rn(l1w[idx]);
    }
    for (int idx = threadIdx.x; idx < 1024; idx += blockDim.x) {
        int h2 = idx >> 5, i = idx & 31;
        g_w2t[i * 32 + h2] = l2w[idx];
    }
}

// ---------------------------------------------------------------------------
// Sparse gather-accumulate: fp16 columns, fp32 accumulation.
// h mapping: acc[j] <-> h = lane*8 + j
// ---------------------------------------------------------------------------
__device__ __forceinline__ void accum_mask(unsigned mask, int fbase, int lane,
                                           float acc[8]) {
    while (mask) {
        int b = __ffs(mask) - 1;
        mask &= mask - 1;
        int f = fbase + b * 4;
        const uint4* wp = (const uint4*)(g_ft_wt_h + (size_t)f * H0);
        uint4 a = __ldg(wp + lane);
        const __half2* hp = (const __half2*)&a;
        float2 f0 = __half22float2(hp[0]);
        float2 f1 = __half22float2(hp[1]);
        float2 f2 = __half22float2(hp[2]);
        float2 f3 = __half22float2(hp[3]);
        acc[0] += f0.x; acc[1] += f0.y;
        acc[2] += f1.x; acc[3] += f1.y;
        acc[4] += f2.x; acc[5] += f2.y;
        acc[6] += f3.x; acc[7] += f3.y;
    }
}

__device__ __forceinline__ void process_chunk(const float4 v[4], int base,
                                              int lane, float acc[8]) {
    #pragma unroll
    for (int c = 0; c < 4; c++) {
        int cb = base + c * 128;
        float s = v[c].x + v[c].y + v[c].z + v[c].w;
        unsigned any = __ballot_sync(0xffffffffu, s != 0.0f);
        if (any) {
            unsigned mx = __ballot_sync(0xffffffffu, v[c].x != 0.0f);
            unsigned my = __ballot_sync(0xffffffffu, v[c].y != 0.0f);
            unsigned mz = __ballot_sync(0xffffffffu, v[c].z != 0.0f);
            unsigned mw = __ballot_sync(0xffffffffu, v[c].w != 0.0f);
            accum_mask(mx, cb + 0, lane, acc);
            accum_mask(my, cb + 1, lane, acc);
            accum_mask(mz, cb + 2, lane, acc);
            accum_mask(mw, cb + 3, lane, acc);
        }
    }
}

// ---------------------------------------------------------------------------
// Fused kernel: scan + full tail, one warp per row, 2 rows per warp.
// Dynamic smem: o0 (8*512 f32) | w1h (512*32 f16) | w2 (32*32 f32) | biases
// ---------------------------------------------------------------------------
#define SM_O0   0                      // 4096 floats
#define SM_W1H  4096                   // (as floats) 16384 halves = 8192 floats... offsets in floats below
#define SM_W2   (4096 + 8192)          // 1024 floats
#define SM_B1   (4096 + 8192 + 1024)   // 32
#define SM_B2   (SM_B1 + 32)           // 32
#define SM_L3W  (SM_B2 + 32)           // 32
#define SM_L3B  (SM_L3W + 32)          // 1
#define SM_TOTALF (SM_L3B + 1)

__global__ __launch_bounds__(256, 4) void nnue_fused_kernel(
    const float* __restrict__ white, const float* __restrict__ black,
    const void* __restrict__ side, const float* __restrict__ ft_b,
    const float* __restrict__ l1_b, const float* __restrict__ l2_b,
    const float* __restrict__ l3_w, const float* __restrict__ l3_b,
    float* __restrict__ out)
{
    extern __shared__ float sm[];
    float*  o0s  = sm + SM_O0;
    __half* w1hs = (__half*)(sm + SM_W1H);
    float*  w2s  = sm + SM_W2;

    int tid = threadIdx.x;

    // Stage tail weights/biases once per block
    {
        const uint4* src = (const uint4*)g_w1h;           // 16384 halves = 2048 uint4
        uint4* dst = (uint4*)w1hs;
        for (int i = tid; i < 2048; i += 256) dst[i] = src[i];
        for (int i = tid; i < 1024; i += 256) w2s[i] = g_w2t[i];
        if (tid < 32) {
            sm[SM_B1 + tid]  = l1_b[tid];
            sm[SM_B2 + tid]  = l2_b[tid];
            sm[SM_L3W + tid] = l3_w[tid];
        }
        if (tid == 0) sm[SM_L3B] = l3_b[0];
    }
    __syncthreads();

    int lane = tid & 31;
    int wrp  = tid >> 5;
    int mode = g_side_mode;

    // bias: h = lane*8 + j
    float4 b0 = __ldg((const float4*)ft_b + lane * 2);
    float4 b1 = __ldg((const float4*)ft_b + lane * 2 + 1);

    float* o  = o0s + wrp * 512;
    const float4* o4 = (const float4*)o;

    int gw = blockIdx.x * WARPS_PER_BLOCK + wrp;   // global warp id

    #pragma unroll 1
    for (int t = 0; t < 2; t++) {
        int r = gw * 2 + t;

        float aw[8] = {b0.x, b0.y, b0.z, b0.w, b1.x, b1.y, b1.z, b1.w};
        float ab[8] = {b0.x, b0.y, b0.z, b0.w, b1.x, b1.y, b1.z, b1.w};

        const float4* wrow = (const float4*)(white + (size_t)r * N_IN);
        const float4* brow = (const float4*)(black + (size_t)r * N_IN);

        for (int base = 0; base < N_IN; base += 512) {
            int q = (base >> 2) + lane;
            float4 wv[4], bv[4];
            #pragma unroll
            for (int c = 0; c < 4; c++) wv[c] = __ldcs(wrow + q + c * 32);
            #pragma unroll
            for (int c = 0; c < 4; c++) bv[c] = __ldcs(brow + q + c * 32);
            process_chunk(wv, base, lane, aw);
            process_chunk(bv, base, lane, ab);
        }

        // side flag
        bool s;
        if (mode == 0)      s = ((const unsigned char*)side)[r] != 0;
        else if (mode == 1) s = ((const int*)side)[r] != 0;
        else                s = ((const float*)side)[r] != 0.0f;

        // clipped o0 = [us(256) | them(256)], h = lane*8 + j
        {
            float us[8], th[8];
            #pragma unroll
            for (int j = 0; j < 8; j++) {
                float u = s ? aw[j] : ab[j];
                float v = s ? ab[j] : aw[j];
                us[j] = fminf(fmaxf(u, 0.0f), 1.0f);
                th[j] = fminf(fmaxf(v, 0.0f), 1.0f);
            }
            float4* ow = (float4*)o;
            ow[lane * 2]          = make_float4(us[0], us[1], us[2], us[3]);
            ow[lane * 2 + 1]      = make_float4(us[4], us[5], us[6], us[7]);
            ow[64 + lane * 2]     = make_float4(th[0], th[1], th[2], th[3]);
            ow[64 + lane * 2 + 1] = make_float4(th[4], th[5], th[6], th[7]);
        }
        __syncwarp();

        // ---- L1: lane h computes o1[h] = clip(b1 + sum_i o0[i]*w1[i][h])
        float s1 = sm[SM_B1 + lane];
        const uint2* w1q = (const uint2*)w1hs;   // [i4*32 + h] -> 4 halves
        #pragma unroll 8
        for (int i4 = 0; i4 < 128; i4++) {
            float4 ov = o4[i4];                  // warp-broadcast
            uint2 wr = w1q[i4 * 32 + lane];
            float2 fa = __half22float2(*(const __half2*)&wr.x);
            float2 fb = __half22float2(*(const __half2*)&wr.y);
            s1 = fmaf(ov.x, fa.x, s1);
            s1 = fmaf(ov.y, fa.y, s1);
            s1 = fmaf(ov.z, fb.x, s1);
            s1 = fmaf(ov.w, fb.y, s1);
        }
        float o1 = fminf(fmaxf(s1, 0.0f), 1.0f);

        // ---- L2: lane h2
        float s2 = sm[SM_B2 + lane];
        #pragma unroll
        for (int i = 0; i < 32; i++) {
            float v = __shfl_sync(0xffffffffu, o1, i);
            s2 = fmaf(v, w2s[i * 32 + lane], s2);
        }
        float o2 = fminf(fmaxf(s2, 0.0f), 1.0f);

        // ---- L3 + sigmoid
        float p = o2 * sm[SM_L3W + lane];
        #pragma unroll
        for (int off = 16; off; off >>= 1)
            p += __shfl_xor_sync(0xffffffffu, p, off);
        if (lane == 0) {
            float tt = (p + sm[SM_L3B]) * 1.5f;   // OUTPUT_SCALE / WDL_SCALE
            out[r] = 1.0f / (1.0f + expf(-tt));
        }
        __syncwarp();
    }
}

// ---------------------------------------------------------------------------
extern "C" void kernel_launch(void* const* d_in, const int* in_sizes, int n_in,
                              void* d_out, int out_size) {
    const float* white = (const float*)d_in[0];
    const float* black = (const float*)d_in[1];
    const void*  side  = d_in[2];
    const float* ft_w  = (const float*)d_in[3];
    const float* ft_b  = (const float*)d_in[4];
    const float* l1_w  = (const float*)d_in[5];
    const float* l1_b  = (const float*)d_in[6];
    const float* l2_w  = (const float*)d_in[7];
    const float* l2_b  = (const float*)d_in[8];
    const float* l3_w  = (const float*)d_in[9];
    const float* l3_b  = (const float*)d_in[10];
    float* out = (float*)d_out;

    const int smem_bytes = SM_TOTALF * 4 + 256;  // ~53.7 KB
    cudaFuncSetAttribute(nnue_fused_kernel,
                         cudaFuncAttributeMaxDynamicSharedMemorySize,
                         smem_bytes);

    side_mode_kernel<<<1, 256>>>((const unsigned char*)side);
    transpose_ft_kernel<<<dim3(N_IN / 32, H0 / 32), dim3(32, 32)>>>(ft_w);
    prep_tail_kernel<<<1, 256>>>(l1_w, l2_w);
    nnue_fused_kernel<<<GRID, 256, smem_bytes>>>(
        white, black, side, ft_b, l1_b, l2_b, l3_w, l3_b, out);
}

// round 5
// speedup vs baseline: 1.2810x; 1.2810x over previous
#include <cuda_runtime.h>
#include <cuda_bf16.h>
#include <cuda_fp16.h>
#include <math.h>

#define N_IN   12288
#define H0     256
#define BATCH  8192
#define ROWS_PER_BLOCK 8

// Scratch (static device allocations are allowed)
__device__ __half g_ft_wt_h[N_IN * H0];   // (12288, 256) transposed, fp16
__device__ float  g_o0[BATCH * 512];      // clipped, side-swapped accumulator
__device__ __half g_w1h[512 * 32];        // l1_w repacked: [i4][h][c] fp16
__device__ float  g_w2t[32 * 32];         // l2_w transposed [i][h2]
__device__ int    g_side_mode;            // 0=uint8, 1=int32, 2=float32

// ---------------------------------------------------------------------------
// Combined prep: side-dtype sniff + tail weight repack (one launch).
// ---------------------------------------------------------------------------
__global__ void prep_kernel(const unsigned char* __restrict__ p,
                            const float* __restrict__ l1w,
                            const float* __restrict__ l2w) {
    __shared__ int c3F, cOdd;
    if (threadIdx.x == 0) { c3F = 0; cOdd = 0; }
    __syncthreads();
    int l3f = 0, lodd = 0;
    for (int i = threadIdx.x; i < 8192; i += blockDim.x) {
        unsigned char b = p[i];
        if ((i & 3) == 3 && b == 0x3F) l3f++;
        if ((i & 3) != 0 && b != 0)    lodd++;
    }
    atomicAdd(&c3F, l3f);
    atomicAdd(&cOdd, lodd);

    // w1 repack: g_w1h[i4*128 + h*4 + c] = half(l1_w[h*512 + i4*4 + c])
    for (int idx = threadIdx.x; idx < 32 * 512; idx += blockDim.x) {
        int h = idx >> 9, i = idx & 511;
        int i4 = i >> 2, c = i & 3;
        g_w1h[i4 * 128 + h * 4 + c] = __float2half_rn(l1w[idx]);
    }
    // w2 transpose: g_w2t[i*32 + h2] = l2_w[h2*32 + i]
    for (int idx = threadIdx.x; idx < 1024; idx += blockDim.x) {
        int h2 = idx >> 5, i = idx & 31;
        g_w2t[i * 32 + h2] = l2w[idx];
    }
    __syncthreads();
    if (threadIdx.x == 0)
        g_side_mode = (c3F > 0) ? 2 : ((cOdd > 0) ? 0 : 1);
}

// ---------------------------------------------------------------------------
// Tiled transpose + fp16 convert: ft_w (256, 12288) -> g_ft_wt_h (12288, 256)
// ---------------------------------------------------------------------------
__global__ void transpose_ft_kernel(const float* __restrict__ ft_w) {
    __shared__ float tile[32][33];
    int f = blockIdx.x * 32 + threadIdx.x;
    int h = blockIdx.y * 32 + threadIdx.y;
    tile[threadIdx.y][threadIdx.x] = ft_w[h * N_IN + f];
    __syncthreads();
    int oh = blockIdx.y * 32 + threadIdx.x;
    int of = blockIdx.x * 32 + threadIdx.y;
    g_ft_wt_h[of * H0 + oh] = __float2half_rn(tile[threadIdx.x][threadIdx.y]);
}

// ---------------------------------------------------------------------------
// Sparse gather-accumulate: fp16 columns, fp32 accumulation.
// h mapping: acc[j] <-> h = lane*8 + j
// ---------------------------------------------------------------------------
__device__ __forceinline__ void accum_mask(unsigned mask, int fbase, int lane,
                                           float acc[8]) {
    while (mask) {
        int b = __ffs(mask) - 1;
        mask &= mask - 1;
        int f = fbase + b * 4;
        const uint4* wp = (const uint4*)(g_ft_wt_h + (size_t)f * H0);
        uint4 a = __ldg(wp + lane);
        const __half2* hp = (const __half2*)&a;
        float2 f0 = __half22float2(hp[0]);
        float2 f1 = __half22float2(hp[1]);
        float2 f2 = __half22float2(hp[2]);
        float2 f3 = __half22float2(hp[3]);
        acc[0] += f0.x; acc[1] += f0.y;
        acc[2] += f1.x; acc[3] += f1.y;
        acc[4] += f2.x; acc[5] += f2.y;
        acc[6] += f3.x; acc[7] += f3.y;
    }
}

__device__ __forceinline__ void process_chunk(const float4 v[4], int base,
                                              int lane, float acc[8]) {
    #pragma unroll
    for (int c = 0; c < 4; c++) {
        int cb = base + c * 128;
        float s = v[c].x + v[c].y + v[c].z + v[c].w;
        unsigned any = __ballot_sync(0xffffffffu, s != 0.0f);
        if (any) {
            unsigned mx = __ballot_sync(0xffffffffu, v[c].x != 0.0f);
            unsigned my = __ballot_sync(0xffffffffu, v[c].y != 0.0f);
            unsigned mz = __ballot_sync(0xffffffffu, v[c].z != 0.0f);
            unsigned mw = __ballot_sync(0xffffffffu, v[c].w != 0.0f);
            accum_mask(mx, cb + 0, lane, acc);
            accum_mask(my, cb + 1, lane, acc);
            accum_mask(mz, cb + 2, lane, acc);
            accum_mask(mw, cb + 3, lane, acc);
        }
    }
}

// ---------------------------------------------------------------------------
// Scan kernel: one warp per batch row, no shared memory. (R3 structure.)
// ---------------------------------------------------------------------------
__global__ __launch_bounds__(256, 4) void nnue_scan_kernel(
    const float* __restrict__ white, const float* __restrict__ black,
    const void* __restrict__ side, const float* __restrict__ ft_b)
{
    int tid  = threadIdx.x;
    int lane = tid & 31;
    int wrp  = tid >> 5;
    int r = blockIdx.x * ROWS_PER_BLOCK + wrp;

    // bias: h = lane*8 + j
    float4 b0 = __ldg((const float4*)ft_b + lane * 2);
    float4 b1 = __ldg((const float4*)ft_b + lane * 2 + 1);
    float aw[8] = {b0.x, b0.y, b0.z, b0.w, b1.x, b1.y, b1.z, b1.w};
    float ab[8] = {b0.x, b0.y, b0.z, b0.w, b1.x, b1.y, b1.z, b1.w};

    const float4* wrow = (const float4*)(white + (size_t)r * N_IN);
    const float4* brow = (const float4*)(black + (size_t)r * N_IN);

    for (int base = 0; base < N_IN; base += 512) {
        int q = (base >> 2) + lane;
        float4 wv[4], bv[4];
        #pragma unroll
        for (int c = 0; c < 4; c++) wv[c] = __ldcs(wrow + q + c * 32);
        #pragma unroll
        for (int c = 0; c < 4; c++) bv[c] = __ldcs(brow + q + c * 32);
        process_chunk(wv, base, lane, aw);
        process_chunk(bv, base, lane, ab);
    }

    // side flag (auto-detected dtype)
    int mode = g_side_mode;
    bool s;
    if (mode == 0)      s = ((const unsigned char*)side)[r] != 0;
    else if (mode == 1) s = ((const int*)side)[r] != 0;
    else                s = ((const float*)side)[r] != 0.0f;

    float us[8], th[8];
    #pragma unroll
    for (int j = 0; j < 8; j++) {
        float u = s ? aw[j] : ab[j];
        float t = s ? ab[j] : aw[j];
        us[j] = fminf(fmaxf(u, 0.0f), 1.0f);
        th[j] = fminf(fmaxf(t, 0.0f), 1.0f);
    }
    // o0 layout: [us(256) | them(256)], index h = lane*8 + j
    float4* o = (float4*)(g_o0 + (size_t)r * 512);
    o[lane * 2]          = make_float4(us[0], us[1], us[2], us[3]);
    o[lane * 2 + 1]      = make_float4(us[4], us[5], us[6], us[7]);
    o[64 + lane * 2]     = make_float4(th[0], th[1], th[2], th[3]);
    o[64 + lane * 2 + 1] = make_float4(th[4], th[5], th[6], th[7]);
}

// ---------------------------------------------------------------------------
// Tail kernel: warp per row, high occupancy (54 KB smem -> 4 blocks/SM).
// smem: o0 slices (8*512 f32) | w1h (512*32 f16) | w2 (32*32 f32) | biases
// ---------------------------------------------------------------------------
#define SM_O0     0
#define SM_W1H    4096                    // float offset; holds 16384 halves
#define SM_W2     (4096 + 8192)
#define SM_B1     (SM_W2 + 1024)
#define SM_B2     (SM_B1 + 32)
#define SM_L3W    (SM_B2 + 32)
#define SM_L3B    (SM_L3W + 32)
#define SM_TOTALF (SM_L3B + 1)

__global__ __launch_bounds__(256, 4) void nnue_tail_kernel(
    const float* __restrict__ l1_b, const float* __restrict__ l2_b,
    const float* __restrict__ l3_w, const float* __restrict__ l3_b,
    float* __restrict__ out)
{
    extern __shared__ float sm[];
    float*  o0s  = sm + SM_O0;
    __half* w1hs = (__half*)(sm + SM_W1H);
    float*  w2s  = sm + SM_W2;

    int tid = threadIdx.x;
    {
        const uint4* src = (const uint4*)g_w1h;   // 16384 halves = 2048 uint4
        uint4* dst = (uint4*)w1hs;
        for (int i = tid; i < 2048; i += 256) dst[i] = __ldg(src + i);
        for (int i = tid; i < 1024; i += 256) w2s[i] = g_w2t[i];
        if (tid < 32) {
            sm[SM_B1 + tid]  = l1_b[tid];
            sm[SM_B2 + tid]  = l2_b[tid];
            sm[SM_L3W + tid] = l3_w[tid];
        }
        if (tid == 0) sm[SM_L3B] = l3_b[0];
    }
    __syncthreads();

    int lane = tid & 31;
    int wrp  = tid >> 5;
    int r = blockIdx.x * ROWS_PER_BLOCK + wrp;

    // Stage this row's o0 into the warp's smem slice (coalesced float4)
    float* o = o0s + wrp * 512;
    const float4* src = (const float4*)(g_o0 + (size_t)r * 512);
    float4* ow = (float4*)o;
    #pragma unroll
    for (int c = 0; c < 4; c++)
        ow[c * 32 + lane] = __ldg(src + c * 32 + lane);
    __syncwarp();

    // ---- L1: lane h computes o1[h]; 4 partial accumulators break the chain
    const float4* o4 = (const float4*)o;
    const uint2* w1q = (const uint2*)w1hs;        // [i4*32 + h] -> 4 halves
    float p0 = sm[SM_B1 + lane], p1 = 0.f, p2 = 0.f, p3 = 0.f;
    #pragma unroll 8
    for (int i4 = 0; i4 < 128; i4++) {
        float4 ov = o4[i4];                       // warp-uniform broadcast
        uint2 wr = w1q[i4 * 32 + lane];
        float2 fa = __half22float2(*(const __half2*)&wr.x);
        float2 fb = __half22float2(*(const __half2*)&wr.y);
        p0 = fmaf(ov.x, fa.x, p0);
        p1 = fmaf(ov.y, fa.y, p1);
        p2 = fmaf(ov.z, fb.x, p2);
        p3 = fmaf(ov.w, fb.y, p3);
    }
    float o1 = fminf(fmaxf((p0 + p1) + (p2 + p3), 0.0f), 1.0f);

    // ---- L2: lane h2
    float s2 = sm[SM_B2 + lane];
    #pragma unroll
    for (int i = 0; i < 32; i++) {
        float v = __shfl_sync(0xffffffffu, o1, i);
        s2 = fmaf(v, w2s[i * 32 + lane], s2);
    }
    float o2 = fminf(fmaxf(s2, 0.0f), 1.0f);

    // ---- L3 + sigmoid
    float p = o2 * sm[SM_L3W + lane];
    #pragma unroll
    for (int off = 16; off; off >>= 1)
        p += __shfl_xor_sync(0xffffffffu, p, off);
    if (lane == 0) {
        float t = (p + sm[SM_L3B]) * 1.5f;   // OUTPUT_SCALE / WDL_SCALE
        out[r] = 1.0f / (1.0f + expf(-t));
    }
}

// ---------------------------------------------------------------------------
extern "C" void kernel_launch(void* const* d_in, const int* in_sizes, int n_in,
                              void* d_out, int out_size) {
    const float* white = (const float*)d_in[0];
    const float* black = (const float*)d_in[1];
    const void*  side  = d_in[2];
    const float* ft_w  = (const float*)d_in[3];
    const float* ft_b  = (const float*)d_in[4];
    const float* l1_w  = (const float*)d_in[5];
    const float* l1_b  = (const float*)d_in[6];
    const float* l2_w  = (const float*)d_in[7];
    const float* l2_b  = (const float*)d_in[8];
    const float* l3_w  = (const float*)d_in[9];
    const float* l3_b  = (const float*)d_in[10];
    float* out = (float*)d_out;

    const int tail_smem = SM_TOTALF * 4 + 128;   // ~53.7 KB
    cudaFuncSetAttribute(nnue_tail_kernel,
                         cudaFuncAttributeMaxDynamicSharedMemorySize,
                         tail_smem);

    prep_kernel<<<1, 256>>>((const unsigned char*)side, l1_w, l2_w);
    transpose_ft_kernel<<<dim3(N_IN / 32, H0 / 32), dim3(32, 32)>>>(ft_w);
    nnue_scan_kernel<<<BATCH / ROWS_PER_BLOCK, 256>>>(white, black, side, ft_b);
    nnue_tail_kernel<<<BATCH / ROWS_PER_BLOCK, 256, tail_smem>>>(
        l1_b, l2_b, l3_w, l3_b, out);
}

// round 6
// speedup vs baseline: 1.3131x; 1.0250x over previous
#include <cuda_runtime.h>
#include <cuda_bf16.h>
#include <cuda_fp16.h>
#include <math.h>

#define N_IN   12288
#define H0     256
#define BATCH  8192
#define ROWS_PER_BLOCK 8
#define TROWS  32                 // rows per tail block

// Scratch (static device allocations are allowed)
__device__ __half g_ft_wt_h[N_IN * H0];   // (12288, 256) transposed, fp16
__device__ __half g_o0h[BATCH * 512];     // clipped, side-swapped o0, fp16
__device__ __half g_w1h[512 * 32];        // l1_w repacked: [i4][h][c] fp16
__device__ float  g_w2t[32 * 32];         // l2_w transposed [i][h2]
__device__ int    g_side_mode;            // 0=uint8, 1=int32, 2=float32

// ---------------------------------------------------------------------------
// Combined prep: side-dtype sniff + tail weight repack (one launch).
// ---------------------------------------------------------------------------
__global__ void prep_kernel(const unsigned char* __restrict__ p,
                            const float* __restrict__ l1w,
                            const float* __restrict__ l2w) {
    __shared__ int c3F, cOdd;
    if (threadIdx.x == 0) { c3F = 0; cOdd = 0; }
    __syncthreads();
    int l3f = 0, lodd = 0;
    for (int i = threadIdx.x; i < 8192; i += blockDim.x) {
        unsigned char b = p[i];
        if ((i & 3) == 3 && b == 0x3F) l3f++;
        if ((i & 3) != 0 && b != 0)    lodd++;
    }
    atomicAdd(&c3F, l3f);
    atomicAdd(&cOdd, lodd);

    // w1 repack: g_w1h[i4*128 + h*4 + c] = half(l1_w[h*512 + i4*4 + c])
    for (int idx = threadIdx.x; idx < 32 * 512; idx += blockDim.x) {
        int h = idx >> 9, i = idx & 511;
        int i4 = i >> 2, c = i & 3;
        g_w1h[i4 * 128 + h * 4 + c] = __float2half_rn(l1w[idx]);
    }
    // w2 transpose: g_w2t[i*32 + h2] = l2_w[h2*32 + i]
    for (int idx = threadIdx.x; idx < 1024; idx += blockDim.x) {
        int h2 = idx >> 5, i = idx & 31;
        g_w2t[i * 32 + h2] = l2w[idx];
    }
    __syncthreads();
    if (threadIdx.x == 0)
        g_side_mode = (c3F > 0) ? 2 : ((cOdd > 0) ? 0 : 1);
}

// ---------------------------------------------------------------------------
// Tiled transpose + fp16 convert: ft_w (256, 12288) -> g_ft_wt_h (12288, 256)
// ---------------------------------------------------------------------------
__global__ void transpose_ft_kernel(const float* __restrict__ ft_w) {
    __shared__ float tile[32][33];
    int f = blockIdx.x * 32 + threadIdx.x;
    int h = blockIdx.y * 32 + threadIdx.y;
    tile[threadIdx.y][threadIdx.x] = ft_w[h * N_IN + f];
    __syncthreads();
    int oh = blockIdx.y * 32 + threadIdx.x;
    int of = blockIdx.x * 32 + threadIdx.y;
    g_ft_wt_h[of * H0 + oh] = __float2half_rn(tile[threadIdx.x][threadIdx.y]);
}

// ---------------------------------------------------------------------------
// Sparse gather-accumulate: fp16 columns, fp32 accumulation.
// h mapping: acc[j] <-> h = lane*8 + j
// ---------------------------------------------------------------------------
__device__ __forceinline__ void accum_mask(unsigned mask, int fbase, int lane,
                                           float acc[8]) {
    while (mask) {
        int b = __ffs(mask) - 1;
        mask &= mask - 1;
        int f = fbase + b * 4;
        const uint4* wp = (const uint4*)(g_ft_wt_h + (size_t)f * H0);
        uint4 a = __ldg(wp + lane);
        const __half2* hp = (const __half2*)&a;
        float2 f0 = __half22float2(hp[0]);
        float2 f1 = __half22float2(hp[1]);
        float2 f2 = __half22float2(hp[2]);
        float2 f3 = __half22float2(hp[3]);
        acc[0] += f0.x; acc[1] += f0.y;
        acc[2] += f1.x; acc[3] += f1.y;
        acc[4] += f2.x; acc[5] += f2.y;
        acc[6] += f3.x; acc[7] += f3.y;
    }
}

__device__ __forceinline__ void process_chunk(const float4 v[4], int base,
                                              int lane, float acc[8]) {
    #pragma unroll
    for (int c = 0; c < 4; c++) {
        int cb = base + c * 128;
        float s = v[c].x + v[c].y + v[c].z + v[c].w;
        unsigned any = __ballot_sync(0xffffffffu, s != 0.0f);
        if (any) {
            unsigned mx = __ballot_sync(0xffffffffu, v[c].x != 0.0f);
            unsigned my = __ballot_sync(0xffffffffu, v[c].y != 0.0f);
            unsigned mz = __ballot_sync(0xffffffffu, v[c].z != 0.0f);
            unsigned mw = __ballot_sync(0xffffffffu, v[c].w != 0.0f);
            accum_mask(mx, cb + 0, lane, acc);
            accum_mask(my, cb + 1, lane, acc);
            accum_mask(mz, cb + 2, lane, acc);
            accum_mask(mw, cb + 3, lane, acc);
        }
    }
}

// ---------------------------------------------------------------------------
// Scan kernel: one warp per batch row, no shared memory.
// ---------------------------------------------------------------------------
__global__ __launch_bounds__(256, 4) void nnue_scan_kernel(
    const float* __restrict__ white, const float* __restrict__ black,
    const void* __restrict__ side, const float* __restrict__ ft_b)
{
    int tid  = threadIdx.x;
    int lane = tid & 31;
    int wrp  = tid >> 5;
    int r = blockIdx.x * ROWS_PER_BLOCK + wrp;

    // bias: h = lane*8 + j
    float4 b0 = __ldg((const float4*)ft_b + lane * 2);
    float4 b1 = __ldg((const float4*)ft_b + lane * 2 + 1);
    float aw[8] = {b0.x, b0.y, b0.z, b0.w, b1.x, b1.y, b1.z, b1.w};
    float ab[8] = {b0.x, b0.y, b0.z, b0.w, b1.x, b1.y, b1.z, b1.w};

    const float4* wrow = (const float4*)(white + (size_t)r * N_IN);
    const float4* brow = (const float4*)(black + (size_t)r * N_IN);

    for (int base = 0; base < N_IN; base += 512) {
        int q = (base >> 2) + lane;
        float4 wv[4], bv[4];
        #pragma unroll
        for (int c = 0; c < 4; c++) wv[c] = __ldcs(wrow + q + c * 32);
        #pragma unroll
        for (int c = 0; c < 4; c++) bv[c] = __ldcs(brow + q + c * 32);
        process_chunk(wv, base, lane, aw);
        process_chunk(bv, base, lane, ab);
    }

    // side flag (auto-detected dtype)
    int mode = g_side_mode;
    bool s;
    if (mode == 0)      s = ((const unsigned char*)side)[r] != 0;
    else if (mode == 1) s = ((const int*)side)[r] != 0;
    else                s = ((const float*)side)[r] != 0.0f;

    float us[8], th[8];
    #pragma unroll
    for (int j = 0; j < 8; j++) {
        float u = s ? aw[j] : ab[j];
        float t = s ? ab[j] : aw[j];
        us[j] = fminf(fmaxf(u, 0.0f), 1.0f);
        th[j] = fminf(fmaxf(t, 0.0f), 1.0f);
    }
    // o0 (fp16): [us(256) | them(256)], index h = lane*8 + j
    __half2 u0 = __floats2half2_rn(us[0], us[1]);
    __half2 u1 = __floats2half2_rn(us[2], us[3]);
    __half2 u2 = __floats2half2_rn(us[4], us[5]);
    __half2 u3 = __floats2half2_rn(us[6], us[7]);
    __half2 t0 = __floats2half2_rn(th[0], th[1]);
    __half2 t1 = __floats2half2_rn(th[2], th[3]);
    __half2 t2 = __floats2half2_rn(th[4], th[5]);
    __half2 t3 = __floats2half2_rn(th[6], th[7]);
    uint4* o = (uint4*)(g_o0h + (size_t)r * 512);
    uint4 pu, pt;
    pu.x = *(unsigned*)&u0; pu.y = *(unsigned*)&u1;
    pu.z = *(unsigned*)&u2; pu.w = *(unsigned*)&u3;
    pt.x = *(unsigned*)&t0; pt.y = *(unsigned*)&t1;
    pt.z = *(unsigned*)&t2; pt.w = *(unsigned*)&t3;
    o[lane]      = pu;     // halves lane*8 .. lane*8+7
    o[32 + lane] = pt;     // halves 256 + lane*8 ..
}

// ---------------------------------------------------------------------------
// Tail kernel: 32 rows/block, warp w owns rows 4w..4w+3, lane = unit h.
// w1 smem reads amortized 4x per warp; o0/o1 reads are warp-uniform bcasts.
// smem (floats): o0h 8192 | w1h 8192 | w2 1024 | o1 1024 | biases 97
// ---------------------------------------------------------------------------
#define SM_O0     0
#define SM_W1H    8192
#define SM_W2     (8192 + 8192)
#define SM_O1     (SM_W2 + 1024)
#define SM_B1     (SM_O1 + 1024)
#define SM_B2     (SM_B1 + 32)
#define SM_L3W    (SM_B2 + 32)
#define SM_L3B    (SM_L3W + 32)
#define SM_TOTALF (SM_L3B + 1)

__global__ __launch_bounds__(256, 3) void nnue_tail_kernel(
    const float* __restrict__ l1_b, const float* __restrict__ l2_b,
    const float* __restrict__ l3_w, const float* __restrict__ l3_b,
    float* __restrict__ out)
{
    extern __shared__ float sm[];
    __half* o0h  = (__half*)(sm + SM_O0);
    __half* w1hs = (__half*)(sm + SM_W1H);
    float*  w2s  = sm + SM_W2;
    float*  o1s  = sm + SM_O1;

    int tid  = threadIdx.x;
    int row0 = blockIdx.x * TROWS;

    // Stage o0 tile (32 rows * 1KB = 2048 uint4) and w1 (2048 uint4)
    {
        const uint4* s0 = (const uint4*)(g_o0h + (size_t)row0 * 512);
        uint4* d0 = (uint4*)o0h;
        for (int i = tid; i < 2048; i += 256) d0[i] = __ldg(s0 + i);
        const uint4* s1 = (const uint4*)g_w1h;
        uint4* d1 = (uint4*)w1hs;
        for (int i = tid; i < 2048; i += 256) d1[i] = __ldg(s1 + i);
        for (int i = tid; i < 1024; i += 256) w2s[i] = g_w2t[i];
        if (tid < 32) {
            sm[SM_B1 + tid]  = l1_b[tid];
            sm[SM_B2 + tid]  = l2_b[tid];
            sm[SM_L3W + tid] = l3_w[tid];
        }
        if (tid == 0) sm[SM_L3B] = l3_b[0];
    }
    __syncthreads();

    int h = tid & 31;    // output unit (L1), then h2 (L2)
    int w = tid >> 5;    // warp -> rows 4w .. 4w+3

    // ---- L1: acc[k] = b1[h] + sum_i o0[4w+k][i] * w1[i][h]
    const uint2* w1q = (const uint2*)w1hs;   // [i4*32 + h] -> 4 halves
    const uint2* o0q = (const uint2*)o0h;    // [row*128 + i4] -> 4 halves
    float acc[4];
    float bias1 = sm[SM_B1 + h];
    #pragma unroll
    for (int k = 0; k < 4; k++) acc[k] = bias1;

    #pragma unroll 4
    for (int i4 = 0; i4 < 128; i4++) {
        uint2 wr = w1q[i4 * 32 + h];
        float2 fa = __half22float2(*(const __half2*)&wr.x);
        float2 fb = __half22float2(*(const __half2*)&wr.y);
        #pragma unroll
        for (int k = 0; k < 4; k++) {
            uint2 ov = o0q[(w * 4 + k) * 128 + i4];   // warp-uniform bcast
            float2 oa = __half22float2(*(const __half2*)&ov.x);
            float2 ob = __half22float2(*(const __half2*)&ov.y);
            acc[k] = fmaf(oa.x, fa.x, acc[k]);
            acc[k] = fmaf(oa.y, fa.y, acc[k]);
            acc[k] = fmaf(ob.x, fb.x, acc[k]);
            acc[k] = fmaf(ob.y, fb.y, acc[k]);
        }
    }
    #pragma unroll
    for (int k = 0; k < 4; k++)
        o1s[(w * 4 + k) * 32 + h] = fminf(fmaxf(acc[k], 0.0f), 1.0f);
    __syncwarp();

    // ---- L2: lane h2 over this warp's 4 rows
    float acc2[4];
    float bias2 = sm[SM_B2 + h];
    #pragma unroll
    for (int k = 0; k < 4; k++) acc2[k] = bias2;
    #pragma unroll 4
    for (int hh = 0; hh < 32; hh++) {
        float wv = w2s[hh * 32 + h];
        #pragma unroll
        for (int k = 0; k < 4; k++)
            acc2[k] = fmaf(o1s[(w * 4 + k) * 32 + hh], wv, acc2[k]);
    }

    // ---- L3 + sigmoid
    float lw = sm[SM_L3W + h];
    float p[4];
    #pragma unroll
    for (int k = 0; k < 4; k++)
        p[k] = fminf(fmaxf(acc2[k], 0.0f), 1.0f) * lw;
    #pragma unroll
    for (int off = 16; off; off >>= 1) {
        #pragma unroll
        for (int k = 0; k < 4; k++)
            p[k] += __shfl_xor_sync(0xffffffffu, p[k], off);
    }
    if (h < 4) {
        float t = (p[h] + sm[SM_L3B]) * 1.5f;   // OUTPUT_SCALE / WDL_SCALE
        out[row0 + w * 4 + h] = 1.0f / (1.0f + expf(-t));
    }
}

// ---------------------------------------------------------------------------
extern "C" void kernel_launch(void* const* d_in, const int* in_sizes, int n_in,
                              void* d_out, int out_size) {
    const float* white = (const float*)d_in[0];
    const float* black = (const float*)d_in[1];
    const void*  side  = d_in[2];
    const float* ft_w  = (const float*)d_in[3];
    const float* ft_b  = (const float*)d_in[4];
    const float* l1_w  = (const float*)d_in[5];
    const float* l1_b  = (const float*)d_in[6];
    const float* l2_w  = (const float*)d_in[7];
    const float* l2_b  = (const float*)d_in[8];
    const float* l3_w  = (const float*)d_in[9];
    const float* l3_b  = (const float*)d_in[10];
    float* out = (float*)d_out;

    const int tail_smem = SM_TOTALF * 4 + 128;   // ~74.3 KB
    cudaFuncSetAttribute(nnue_tail_kernel,
                         cudaFuncAttributeMaxDynamicSharedMemorySize,
                         tail_smem);

    prep_kernel<<<1, 256>>>((const unsigned char*)side, l1_w, l2_w);
    transpose_ft_kernel<<<dim3(N_IN / 32, H0 / 32), dim3(32, 32)>>>(ft_w);
    nnue_scan_kernel<<<BATCH / ROWS_PER_BLOCK, 256>>>(white, black, side, ft_b);
    nnue_tail_kernel<<<BATCH / TROWS, 256, tail_smem>>>(
        l1_b, l2_b, l3_w, l3_b, out);
}

// round 7
// speedup vs baseline: 1.3995x; 1.0658x over previous
#include <cuda_runtime.h>
#include <cuda_bf16.h>
#include <cuda_fp16.h>
#include <math.h>

#define N_IN   12288
#define H0     256
#define BATCH  8192
#define ROWS_PER_BLOCK 8
#define TR     32                 // rows per tail block

// Scratch (static device allocations are allowed)
__device__ __half g_ft_wt_h[N_IN * H0];   // (12288, 256) transposed, fp16
__device__ __half g_o0h[BATCH * 512];     // clipped, side-swapped o0, fp16
__device__ uint2  g_w1bf[4096];           // w1 B-fragments: [(kc*4+nt)*32+lane]
__device__ float  g_w2t[32 * 32];         // l2_w transposed [i][h2]
__device__ int    g_side_mode;            // 0=uint8, 1=int32, 2=float32

__device__ __forceinline__ unsigned smem_u32(const void* p) {
    unsigned a;
    asm("{ .reg .u64 t; cvta.to.shared.u64 t, %1; cvt.u32.u64 %0, t; }"
        : "=r"(a) : "l"(p));
    return a;
}

// ---------------------------------------------------------------------------
// Combined prep: side sniff + w1 B-fragment build + w2 transpose.
// B fragment (m16n8k16 col-major B): lane holds
//   .x = half2(B[k0][n], B[k0+1][n]), .y = half2(B[k0+8][n], B[k0+9][n])
// with k0 = (lane%4)*2, n = nt*8 + lane/4; B[k][n] = l1_w[n*512 + k].
// ---------------------------------------------------------------------------
__global__ void prep_kernel(const unsigned char* __restrict__ p,
                            const float* __restrict__ l1w,
                            const float* __restrict__ l2w) {
    __shared__ int c3F, cOdd;
    if (threadIdx.x == 0) { c3F = 0; cOdd = 0; }
    __syncthreads();
    int l3f = 0, lodd = 0;
    for (int i = threadIdx.x; i < 8192; i += blockDim.x) {
        unsigned char b = p[i];
        if ((i & 3) == 3 && b == 0x3F) l3f++;
        if ((i & 3) != 0 && b != 0)    lodd++;
    }
    atomicAdd(&c3F, l3f);
    atomicAdd(&cOdd, lodd);

    for (int idx = threadIdx.x; idx < 4096; idx += blockDim.x) {
        int lane = idx & 31;
        int t    = idx >> 5;
        int nt   = t & 3;
        int kc   = t >> 2;
        int k0   = kc * 16 + (lane & 3) * 2;
        int n    = nt * 8 + (lane >> 2);
        __half2 x = __floats2half2_rn(l1w[n * 512 + k0],     l1w[n * 512 + k0 + 1]);
        __half2 y = __floats2half2_rn(l1w[n * 512 + k0 + 8], l1w[n * 512 + k0 + 9]);
        uint2 v;
        v.x = *(unsigned*)&x;
        v.y = *(unsigned*)&y;
        g_w1bf[idx] = v;
    }
    for (int idx = threadIdx.x; idx < 1024; idx += blockDim.x) {
        int h2 = idx >> 5, i = idx & 31;
        g_w2t[i * 32 + h2] = l2w[idx];
    }
    __syncthreads();
    if (threadIdx.x == 0)
        g_side_mode = (c3F > 0) ? 2 : ((cOdd > 0) ? 0 : 1);
}

// ---------------------------------------------------------------------------
// Tiled transpose + fp16 convert: ft_w (256, 12288) -> g_ft_wt_h (12288, 256)
// ---------------------------------------------------------------------------
__global__ void transpose_ft_kernel(const float* __restrict__ ft_w) {
    __shared__ float tile[32][33];
    int f = blockIdx.x * 32 + threadIdx.x;
    int h = blockIdx.y * 32 + threadIdx.y;
    tile[threadIdx.y][threadIdx.x] = ft_w[h * N_IN + f];
    __syncthreads();
    int oh = blockIdx.y * 32 + threadIdx.x;
    int of = blockIdx.x * 32 + threadIdx.y;
    g_ft_wt_h[of * H0 + oh] = __float2half_rn(tile[threadIdx.x][threadIdx.y]);
}

// ---------------------------------------------------------------------------
// Sparse gather-accumulate (scan): fp16 columns, fp32 accumulation.
// ---------------------------------------------------------------------------
__device__ __forceinline__ void accum_mask(unsigned mask, int fbase, int lane,
                                           float acc[8]) {
    while (mask) {
        int b = __ffs(mask) - 1;
        mask &= mask - 1;
        int f = fbase + b * 4;
        const uint4* wp = (const uint4*)(g_ft_wt_h + (size_t)f * H0);
        uint4 a = __ldg(wp + lane);
        const __half2* hp = (const __half2*)&a;
        float2 f0 = __half22float2(hp[0]);
        float2 f1 = __half22float2(hp[1]);
        float2 f2 = __half22float2(hp[2]);
        float2 f3 = __half22float2(hp[3]);
        acc[0] += f0.x; acc[1] += f0.y;
        acc[2] += f1.x; acc[3] += f1.y;
        acc[4] += f2.x; acc[5] += f2.y;
        acc[6] += f3.x; acc[7] += f3.y;
    }
}

__device__ __forceinline__ void process_chunk(const float4 v[4], int base,
                                              int lane, float acc[8]) {
    #pragma unroll
    for (int c = 0; c < 4; c++) {
        int cb = base + c * 128;
        float s = v[c].x + v[c].y + v[c].z + v[c].w;
        unsigned any = __ballot_sync(0xffffffffu, s != 0.0f);
        if (any) {
            unsigned mx = __ballot_sync(0xffffffffu, v[c].x != 0.0f);
            unsigned my = __ballot_sync(0xffffffffu, v[c].y != 0.0f);
            unsigned mz = __ballot_sync(0xffffffffu, v[c].z != 0.0f);
            unsigned mw = __ballot_sync(0xffffffffu, v[c].w != 0.0f);
            accum_mask(mx, cb + 0, lane, acc);
            accum_mask(my, cb + 1, lane, acc);
            accum_mask(mz, cb + 2, lane, acc);
            accum_mask(mw, cb + 3, lane, acc);
        }
    }
}

// ---------------------------------------------------------------------------
// Scan kernel: one warp per batch row, no shared memory.
// ---------------------------------------------------------------------------
__global__ __launch_bounds__(256, 4) void nnue_scan_kernel(
    const float* __restrict__ white, const float* __restrict__ black,
    const void* __restrict__ side, const float* __restrict__ ft_b)
{
    int tid  = threadIdx.x;
    int lane = tid & 31;
    int wrp  = tid >> 5;
    int r = blockIdx.x * ROWS_PER_BLOCK + wrp;

    float4 b0 = __ldg((const float4*)ft_b + lane * 2);
    float4 b1 = __ldg((const float4*)ft_b + lane * 2 + 1);
    float aw[8] = {b0.x, b0.y, b0.z, b0.w, b1.x, b1.y, b1.z, b1.w};
    float ab[8] = {b0.x, b0.y, b0.z, b0.w, b1.x, b1.y, b1.z, b1.w};

    const float4* wrow = (const float4*)(white + (size_t)r * N_IN);
    const float4* brow = (const float4*)(black + (size_t)r * N_IN);

    for (int base = 0; base < N_IN; base += 512) {
        int q = (base >> 2) + lane;
        float4 wv[4], bv[4];
        #pragma unroll
        for (int c = 0; c < 4; c++) wv[c] = __ldcs(wrow + q + c * 32);
        #pragma unroll
        for (int c = 0; c < 4; c++) bv[c] = __ldcs(brow + q + c * 32);
        process_chunk(wv, base, lane, aw);
        process_chunk(bv, base, lane, ab);
    }

    int mode = g_side_mode;
    bool s;
    if (mode == 0)      s = ((const unsigned char*)side)[r] != 0;
    else if (mode == 1) s = ((const int*)side)[r] != 0;
    else                s = ((const float*)side)[r] != 0.0f;

    float us[8], th[8];
    #pragma unroll
    for (int j = 0; j < 8; j++) {
        float u = s ? aw[j] : ab[j];
        float t = s ? ab[j] : aw[j];
        us[j] = fminf(fmaxf(u, 0.0f), 1.0f);
        th[j] = fminf(fmaxf(t, 0.0f), 1.0f);
    }
    __half2 u0 = __floats2half2_rn(us[0], us[1]);
    __half2 u1 = __floats2half2_rn(us[2], us[3]);
    __half2 u2 = __floats2half2_rn(us[4], us[5]);
    __half2 u3 = __floats2half2_rn(us[6], us[7]);
    __half2 t0 = __floats2half2_rn(th[0], th[1]);
    __half2 t1 = __floats2half2_rn(th[2], th[3]);
    __half2 t2 = __floats2half2_rn(th[4], th[5]);
    __half2 t3 = __floats2half2_rn(th[6], th[7]);
    uint4* o = (uint4*)(g_o0h + (size_t)r * 512);
    uint4 pu, pt;
    pu.x = *(unsigned*)&u0; pu.y = *(unsigned*)&u1;
    pu.z = *(unsigned*)&u2; pu.w = *(unsigned*)&u3;
    pt.x = *(unsigned*)&t0; pt.y = *(unsigned*)&t1;
    pt.z = *(unsigned*)&t2; pt.w = *(unsigned*)&t3;
    o[lane]      = pu;
    o[32 + lane] = pt;
}

// ---------------------------------------------------------------------------
// Tail kernel (tensor core): 32 rows/block, 128 threads (4 warps), grid 256.
// Warp (rt, np): rt = wid>>1 rows rt*16..+15; np = wid&1 cols np*16..+15.
// L1 via mma.m16n8k16, then scalar L2/L3.
// ---------------------------------------------------------------------------
#define O0_STRIDE 520      // halves per staged row (conflict-free ldmatrix)

__global__ __launch_bounds__(128, 2) void nnue_tail_kernel(
    const float* __restrict__ l1_b, const float* __restrict__ l2_b,
    const float* __restrict__ l3_w, const float* __restrict__ l3_b,
    float* __restrict__ out)
{
    extern __shared__ char smraw[];
    __half* o0s  = (__half*)smraw;                         // 32*520 halves = 33280B
    uint2*  bfr  = (uint2*)(smraw + 33280);                // 4096 uint2   = 32768B
    float*  o1s  = (float*)(smraw + 33280 + 32768);        // 32*33        = 4224B
    float*  w2s  = (float*)(smraw + 33280 + 32768 + 4224); // 1024         = 4096B
    float*  bia  = (float*)(smraw + 33280 + 32768 + 4224 + 4096); // 97 floats

    int tid  = threadIdx.x;
    int row0 = blockIdx.x * TR;

    // Stage o0 (32 rows x 512 halves -> stride 520) : 64 uint4 per row
    {
        const uint4* src = (const uint4*)(g_o0h + (size_t)row0 * 512);
        uint4* dst = (uint4*)o0s;                 // 65 uint4 per row (520 halves)
        for (int i = tid; i < TR * 64; i += 128) {
            int r = i >> 6, c = i & 63;
            dst[r * 65 + c] = __ldg(src + i);
        }
        const uint4* bs = (const uint4*)g_w1bf;   // 2048 uint4
        uint4* bd = (uint4*)bfr;
        for (int i = tid; i < 2048; i += 128) bd[i] = __ldg(bs + i);
        for (int i = tid; i < 1024; i += 128) w2s[i] = g_w2t[i];
        if (tid < 32) {
            bia[tid]      = l1_b[tid];
            bia[32 + tid] = l2_b[tid];
            bia[64 + tid] = l3_w[tid];
        }
        if (tid == 0) bia[96] = l3_b[0];
    }
    __syncthreads();

    int lane = tid & 31;
    int wid  = tid >> 5;
    int rt   = wid >> 1;        // row tile (0..1): rows rt*16..+15
    int np   = wid & 1;         // n pair (0..1): cols np*16..+15

    // ldmatrix source address for this lane (x4: T0 rows0-7 k0, T1 rows8-15 k0,
    // T2 rows0-7 k8, T3 rows8-15 k8)
    int arow = rt * 16 + (lane & 7) + ((lane >> 3) & 1) * 8;
    int akoф = ((lane >> 4) & 1) * 8;
    unsigned abase = smem_u32(o0s) + (arow * O0_STRIDE + akoф) * 2;

    float c0[4] = {0.f, 0.f, 0.f, 0.f};
    float c1[4] = {0.f, 0.f, 0.f, 0.f};

    #pragma unroll 4
    for (int kc = 0; kc < 32; kc++) {
        unsigned a0, a1, a2, a3;
        asm volatile(
            "ldmatrix.sync.aligned.m8n8.x4.shared.b16 {%0,%1,%2,%3}, [%4];"
            : "=r"(a0), "=r"(a1), "=r"(a2), "=r"(a3)
            : "r"(abase + kc * 32));
        uint2 bA = bfr[(kc * 4 + np * 2 + 0) * 32 + lane];
        uint2 bB = bfr[(kc * 4 + np * 2 + 1) * 32 + lane];
        asm volatile(
            "mma.sync.aligned.m16n8k16.row.col.f32.f16.f16.f32 "
            "{%0,%1,%2,%3}, {%4,%5,%6,%7}, {%8,%9}, {%0,%1,%2,%3};"
            : "+f"(c0[0]), "+f"(c0[1]), "+f"(c0[2]), "+f"(c0[3])
            : "r"(a0), "r"(a1), "r"(a2), "r"(a3), "r"(bA.x), "r"(bA.y));
        asm volatile(
            "mma.sync.aligned.m16n8k16.row.col.f32.f16.f16.f32 "
            "{%0,%1,%2,%3}, {%4,%5,%6,%7}, {%8,%9}, {%0,%1,%2,%3};"
            : "+f"(c1[0]), "+f"(c1[1]), "+f"(c1[2]), "+f"(c1[3])
            : "r"(a0), "r"(a1), "r"(a2), "r"(a3), "r"(bB.x), "r"(bB.y));
    }

    // Epilogue: bias + clip -> o1s.  C frag: c0,c1 = row lane/4, cols col0,col0+1;
    // c2,c3 = row lane/4+8.
    {
        int rloc = rt * 16 + (lane >> 2);
        int cA = np * 16 + (lane & 3) * 2;          // n-tile np*2
        int cB = cA + 8;                             // n-tile np*2+1
        float bA0 = bia[cA], bA1 = bia[cA + 1];
        float bB0 = bia[cB], bB1 = bia[cB + 1];
        o1s[rloc * 33 + cA]     = fminf(fmaxf(c0[0] + bA0, 0.f), 1.f);
        o1s[rloc * 33 + cA + 1] = fminf(fmaxf(c0[1] + bA1, 0.f), 1.f);
        o1s[(rloc + 8) * 33 + cA]     = fminf(fmaxf(c0[2] + bA0, 0.f), 1.f);
        o1s[(rloc + 8) * 33 + cA + 1] = fminf(fmaxf(c0[3] + bA1, 0.f), 1.f);
        o1s[rloc * 33 + cB]     = fminf(fmaxf(c1[0] + bB0, 0.f), 1.f);
        o1s[rloc * 33 + cB + 1] = fminf(fmaxf(c1[1] + bB1, 0.f), 1.f);
        o1s[(rloc + 8) * 33 + cB]     = fminf(fmaxf(c1[2] + bB0, 0.f), 1.f);
        o1s[(rloc + 8) * 33 + cB + 1] = fminf(fmaxf(c1[3] + bB1, 0.f), 1.f);
    }
    __syncthreads();

    // ---- L2/L3: warp w handles rows w*8..w*8+7, lane = h2
    float acc2[8];
    float bias2 = bia[32 + lane];
    #pragma unroll
    for (int k = 0; k < 8; k++) acc2[k] = bias2;
    #pragma unroll 4
    for (int hh = 0; hh < 32; hh++) {
        float wv = w2s[hh * 32 + lane];
        #pragma unroll
        for (int k = 0; k < 8; k++)
            acc2[k] = fmaf(o1s[(wid * 8 + k) * 33 + hh], wv, acc2[k]);
    }
    float lw = bia[64 + lane];
    float p[8];
    #pragma unroll
    for (int k = 0; k < 8; k++)
        p[k] = fminf(fmaxf(acc2[k], 0.f), 1.f) * lw;
    #pragma unroll
    for (int off = 16; off; off >>= 1) {
        #pragma unroll
        for (int k = 0; k < 8; k++)
            p[k] += __shfl_xor_sync(0xffffffffu, p[k], off);
    }
    if (lane < 8) {
        float t = (p[lane] + bia[96]) * 1.5f;   // OUTPUT_SCALE / WDL_SCALE
        out[row0 + wid * 8 + lane] = 1.0f / (1.0f + expf(-t));
    }
}

// ---------------------------------------------------------------------------
extern "C" void kernel_launch(void* const* d_in, const int* in_sizes, int n_in,
                              void* d_out, int out_size) {
    const float* white = (const float*)d_in[0];
    const float* black = (const float*)d_in[1];
    const void*  side  = d_in[2];
    const float* ft_w  = (const float*)d_in[3];
    const float* ft_b  = (const float*)d_in[4];
    const float* l1_w  = (const float*)d_in[5];
    const float* l1_b  = (const float*)d_in[6];
    const float* l2_w  = (const float*)d_in[7];
    const float* l2_b  = (const float*)d_in[8];
    const float* l3_w  = (const float*)d_in[9];
    const float* l3_b  = (const float*)d_in[10];
    float* out = (float*)d_out;

    const int tail_smem = 33280 + 32768 + 4224 + 4096 + 512;   // ~74.9 KB
    cudaFuncSetAttribute(nnue_tail_kernel,
                         cudaFuncAttributeMaxDynamicSharedMemorySize,
                         tail_smem);

    prep_kernel<<<1, 256>>>((const unsigned char*)side, l1_w, l2_w);
    transpose_ft_kernel<<<dim3(N_IN / 32, H0 / 32), dim3(32, 32)>>>(ft_w);
    nnue_scan_kernel<<<BATCH / ROWS_PER_BLOCK, 256>>>(white, black, side, ft_b);
    nnue_tail_kernel<<<BATCH / TR, 128, tail_smem>>>(
        l1_b, l2_b, l3_w, l3_b, out);
}

// round 8
// speedup vs baseline: 1.4416x; 1.0301x over previous
#include <cuda_runtime.h>
#include <cuda_bf16.h>
#include <cuda_fp16.h>
#include <math.h>

#define N_IN   12288
#define H0     256
#define BATCH  8192
#define RPB    16                 // rows per fused block (one per warp)
#define O0_STRIDE 520             // halves per smem o0 row

// Scratch (static device allocations are allowed)
__device__ __half g_ft_wt_h[N_IN * H0];   // (12288, 256) transposed, fp16
__device__ uint2  g_w1bf[4096];           // w1 B-fragments [(kc*4+nt)*32+lane]
__device__ float  g_w2t[32 * 32];         // l2_w transposed [i][h2]
__device__ int    g_side_mode;            // 0=uint8, 1=int32, 2=float32

__device__ __forceinline__ unsigned smem_u32(const void* p) {
    unsigned a;
    asm("{ .reg .u64 t; cvta.to.shared.u64 t, %1; cvt.u32.u64 %0, t; }"
        : "=r"(a) : "l"(p));
    return a;
}

// ---------------------------------------------------------------------------
// Combined prep: side sniff + w1 B-fragment build + w2 transpose.
// B frag (m16n8k16 col-major B): lane holds
//   .x = half2(B[k0][n], B[k0+1][n]), .y = half2(B[k0+8][n], B[k0+9][n])
// k0 = kc*16 + (lane%4)*2, n = nt*8 + lane/4; B[k][n] = l1_w[n*512 + k].
// ---------------------------------------------------------------------------
__global__ void prep_kernel(const unsigned char* __restrict__ p,
                            const float* __restrict__ l1w,
                            const float* __restrict__ l2w) {
    __shared__ int c3F, cOdd;
    if (threadIdx.x == 0) { c3F = 0; cOdd = 0; }
    __syncthreads();
    int l3f = 0, lodd = 0;
    for (int i = threadIdx.x; i < 8192; i += blockDim.x) {
        unsigned char b = p[i];
        if ((i & 3) == 3 && b == 0x3F) l3f++;
        if ((i & 3) != 0 && b != 0)    lodd++;
    }
    atomicAdd(&c3F, l3f);
    atomicAdd(&cOdd, lodd);

    for (int idx = threadIdx.x; idx < 4096; idx += blockDim.x) {
        int lane = idx & 31;
        int t    = idx >> 5;
        int nt   = t & 3;
        int kc   = t >> 2;
        int k0   = kc * 16 + (lane & 3) * 2;
        int n    = nt * 8 + (lane >> 2);
        __half2 x = __floats2half2_rn(l1w[n * 512 + k0],     l1w[n * 512 + k0 + 1]);
        __half2 y = __floats2half2_rn(l1w[n * 512 + k0 + 8], l1w[n * 512 + k0 + 9]);
        uint2 v;
        v.x = *(unsigned*)&x;
        v.y = *(unsigned*)&y;
        g_w1bf[idx] = v;
    }
    for (int idx = threadIdx.x; idx < 1024; idx += blockDim.x) {
        int h2 = idx >> 5, i = idx & 31;
        g_w2t[i * 32 + h2] = l2w[idx];
    }
    __syncthreads();
    if (threadIdx.x == 0)
        g_side_mode = (c3F > 0) ? 2 : ((cOdd > 0) ? 0 : 1);
}

// ---------------------------------------------------------------------------
// Tiled transpose + fp16 convert: ft_w (256, 12288) -> g_ft_wt_h (12288, 256)
// ---------------------------------------------------------------------------
__global__ void transpose_ft_kernel(const float* __restrict__ ft_w) {
    __shared__ float tile[32][33];
    int f = blockIdx.x * 32 + threadIdx.x;
    int h = blockIdx.y * 32 + threadIdx.y;
    tile[threadIdx.y][threadIdx.x] = ft_w[h * N_IN + f];
    __syncthreads();
    int oh = blockIdx.y * 32 + threadIdx.x;
    int of = blockIdx.x * 32 + threadIdx.y;
    g_ft_wt_h[of * H0 + oh] = __float2half_rn(tile[threadIdx.x][threadIdx.y]);
}

// ---------------------------------------------------------------------------
// Sparse gather-accumulate (scan): fp16 columns, fp32 accumulation.
// h mapping: acc[j] <-> h = lane*8 + j
// ---------------------------------------------------------------------------
__device__ __forceinline__ void accum_mask(unsigned mask, int fbase, int lane,
                                           float acc[8]) {
    while (mask) {
        int b = __ffs(mask) - 1;
        mask &= mask - 1;
        int f = fbase + b * 4;
        const uint4* wp = (const uint4*)(g_ft_wt_h + (size_t)f * H0);
        uint4 a = __ldg(wp + lane);
        const __half2* hp = (const __half2*)&a;
        float2 f0 = __half22float2(hp[0]);
        float2 f1 = __half22float2(hp[1]);
        float2 f2 = __half22float2(hp[2]);
        float2 f3 = __half22float2(hp[3]);
        acc[0] += f0.x; acc[1] += f0.y;
        acc[2] += f1.x; acc[3] += f1.y;
        acc[4] += f2.x; acc[5] += f2.y;
        acc[6] += f3.x; acc[7] += f3.y;
    }
}

__device__ __forceinline__ void process_chunk(const float4 v[4], int base,
                                              int lane, float acc[8]) {
    #pragma unroll
    for (int c = 0; c < 4; c++) {
        int cb = base + c * 128;
        float s = v[c].x + v[c].y + v[c].z + v[c].w;
        unsigned any = __ballot_sync(0xffffffffu, s != 0.0f);
        if (any) {
            unsigned mx = __ballot_sync(0xffffffffu, v[c].x != 0.0f);
            unsigned my = __ballot_sync(0xffffffffu, v[c].y != 0.0f);
            unsigned mz = __ballot_sync(0xffffffffu, v[c].z != 0.0f);
            unsigned mw = __ballot_sync(0xffffffffu, v[c].w != 0.0f);
            accum_mask(mx, cb + 0, lane, acc);
            accum_mask(my, cb + 1, lane, acc);
            accum_mask(mz, cb + 2, lane, acc);
            accum_mask(mw, cb + 3, lane, acc);
        }
    }
}

// ---------------------------------------------------------------------------
// Fused kernel: 16 warps scan 16 rows -> smem o0 -> tensor-core tail.
// smem: o0 (16*520 f16) | bfr (4096 uint2) | o1 (16*33 f32) | w2 | biases
// ---------------------------------------------------------------------------
__global__ __launch_bounds__(512, 2) void nnue_fused_kernel(
    const float* __restrict__ white, const float* __restrict__ black,
    const void* __restrict__ side, const float* __restrict__ ft_b,
    const float* __restrict__ l1_b, const float* __restrict__ l2_b,
    const float* __restrict__ l3_w, const float* __restrict__ l3_b,
    float* __restrict__ out)
{
    extern __shared__ char smraw[];
    __half* o0s = (__half*)smraw;                          // 16*520*2 = 16640B
    uint2*  bfr = (uint2*)(smraw + 16640);                 // 32768B
    float*  o1s = (float*)(smraw + 16640 + 32768);         // 16*33*4 = 2112B
    float*  w2s = (float*)(smraw + 16640 + 32768 + 2112);  // 4096B
    float*  bia = (float*)(smraw + 16640 + 32768 + 2112 + 4096); // 97 floats

    int tid  = threadIdx.x;
    int lane = tid & 31;
    int wid  = tid >> 5;

    // Stage tail constants (cheap, L2-hot)
    {
        const uint4* bs = (const uint4*)g_w1bf;   // 2048 uint4
        uint4* bd = (uint4*)bfr;
        for (int i = tid; i < 2048; i += 512) bd[i] = __ldg(bs + i);
        for (int i = tid; i < 1024; i += 512) w2s[i] = g_w2t[i];
        if (tid < 32) {
            bia[tid]      = l1_b[tid];
            bia[32 + tid] = l2_b[tid];
            bia[64 + tid] = l3_w[tid];
        }
        if (tid == 0) bia[96] = l3_b[0];
    }

    // ---- Scan: warp wid handles row r
    int r = blockIdx.x * RPB + wid;

    float4 b0 = __ldg((const float4*)ft_b + lane * 2);
    float4 b1 = __ldg((const float4*)ft_b + lane * 2 + 1);
    float aw[8] = {b0.x, b0.y, b0.z, b0.w, b1.x, b1.y, b1.z, b1.w};
    float ab[8] = {b0.x, b0.y, b0.z, b0.w, b1.x, b1.y, b1.z, b1.w};

    const float4* wrow = (const float4*)(white + (size_t)r * N_IN);
    const float4* brow = (const float4*)(black + (size_t)r * N_IN);

    for (int base = 0; base < N_IN; base += 512) {
        int q = (base >> 2) + lane;
        float4 wv[4], bv[4];
        #pragma unroll
        for (int c = 0; c < 4; c++) wv[c] = __ldcs(wrow + q + c * 32);
        #pragma unroll
        for (int c = 0; c < 4; c++) bv[c] = __ldcs(brow + q + c * 32);
        process_chunk(wv, base, lane, aw);
        process_chunk(bv, base, lane, ab);
    }

    int mode = g_side_mode;
    bool s;
    if (mode == 0)      s = ((const unsigned char*)side)[r] != 0;
    else if (mode == 1) s = ((const int*)side)[r] != 0;
    else                s = ((const float*)side)[r] != 0.0f;

    float us[8], th[8];
    #pragma unroll
    for (int j = 0; j < 8; j++) {
        float u = s ? aw[j] : ab[j];
        float t = s ? ab[j] : aw[j];
        us[j] = fminf(fmaxf(u, 0.0f), 1.0f);
        th[j] = fminf(fmaxf(t, 0.0f), 1.0f);
    }
    // write o0 row (fp16) to smem: halves [lane*8 .. +8) and [256+lane*8 ..)
    {
        __half2 u0 = __floats2half2_rn(us[0], us[1]);
        __half2 u1 = __floats2half2_rn(us[2], us[3]);
        __half2 u2 = __floats2half2_rn(us[4], us[5]);
        __half2 u3 = __floats2half2_rn(us[6], us[7]);
        __half2 t0 = __floats2half2_rn(th[0], th[1]);
        __half2 t1 = __floats2half2_rn(th[2], th[3]);
        __half2 t2 = __floats2half2_rn(th[4], th[5]);
        __half2 t3 = __floats2half2_rn(th[6], th[7]);
        uint4 pu, pt;
        pu.x = *(unsigned*)&u0; pu.y = *(unsigned*)&u1;
        pu.z = *(unsigned*)&u2; pu.w = *(unsigned*)&u3;
        pt.x = *(unsigned*)&t0; pt.y = *(unsigned*)&t1;
        pt.z = *(unsigned*)&t2; pt.w = *(unsigned*)&t3;
        uint4* orow = (uint4*)(o0s + wid * O0_STRIDE);   // 65 uint4 per row
        orow[lane]      = pu;
        orow[32 + lane] = pt;
    }
    __syncthreads();

    // ---- L1 via tensor cores: warps 0-3, warp nt owns n-tile nt (cols nt*8..+7)
    if (wid < 4) {
        int nt = wid;
        int arow = (lane & 7) + ((lane >> 3) & 1) * 8;
        int akof = ((lane >> 4) & 1) * 8;
        unsigned abase = smem_u32(o0s) + (arow * O0_STRIDE + akof) * 2;

        float c[4] = {0.f, 0.f, 0.f, 0.f};
        #pragma unroll 4
        for (int kc = 0; kc < 32; kc++) {
            unsigned a0, a1, a2, a3;
            asm volatile(
                "ldmatrix.sync.aligned.m8n8.x4.shared.b16 {%0,%1,%2,%3}, [%4];"
                : "=r"(a0), "=r"(a1), "=r"(a2), "=r"(a3)
                : "r"(abase + kc * 32));
            uint2 bB = bfr[(kc * 4 + nt) * 32 + lane];
            asm volatile(
                "mma.sync.aligned.m16n8k16.row.col.f32.f16.f16.f32 "
                "{%0,%1,%2,%3}, {%4,%5,%6,%7}, {%8,%9}, {%0,%1,%2,%3};"
                : "+f"(c[0]), "+f"(c[1]), "+f"(c[2]), "+f"(c[3])
                : "r"(a0), "r"(a1), "r"(a2), "r"(a3), "r"(bB.x), "r"(bB.y));
        }
        // epilogue: bias + clip -> o1s
        int rloc = lane >> 2;
        int col  = nt * 8 + (lane & 3) * 2;
        float bc0 = bia[col], bc1 = bia[col + 1];
        o1s[rloc * 33 + col]           = fminf(fmaxf(c[0] + bc0, 0.f), 1.f);
        o1s[rloc * 33 + col + 1]       = fminf(fmaxf(c[1] + bc1, 0.f), 1.f);
        o1s[(rloc + 8) * 33 + col]     = fminf(fmaxf(c[2] + bc0, 0.f), 1.f);
        o1s[(rloc + 8) * 33 + col + 1] = fminf(fmaxf(c[3] + bc1, 0.f), 1.f);
    }
    __syncthreads();

    // ---- L2/L3: warps 0-1, warp w rows w*8..w*8+7, lane = h2
    if (wid < 2) {
        float acc2[8];
        float bias2 = bia[32 + lane];
        #pragma unroll
        for (int k = 0; k < 8; k++) acc2[k] = bias2;
        #pragma unroll 4
        for (int hh = 0; hh < 32; hh++) {
            float wv = w2s[hh * 32 + lane];
            #pragma unroll
            for (int k = 0; k < 8; k++)
                acc2[k] = fmaf(o1s[(wid * 8 + k) * 33 + hh], wv, acc2[k]);
        }
        float lw = bia[64 + lane];
        float p[8];
        #pragma unroll
        for (int k = 0; k < 8; k++)
            p[k] = fminf(fmaxf(acc2[k], 0.f), 1.f) * lw;
        #pragma unroll
        for (int off = 16; off; off >>= 1) {
            #pragma unroll
            for (int k = 0; k < 8; k++)
                p[k] += __shfl_xor_sync(0xffffffffu, p[k], off);
        }
        if (lane < 8) {
            float t = (p[lane] + bia[96]) * 1.5f;   // OUTPUT_SCALE / WDL_SCALE
            out[blockIdx.x * RPB + wid * 8 + lane] = 1.0f / (1.0f + expf(-t));
        }
    }
}

// ---------------------------------------------------------------------------
extern "C" void kernel_launch(void* const* d_in, const int* in_sizes, int n_in,
                              void* d_out, int out_size) {
    const float* white = (const float*)d_in[0];
    const float* black = (const float*)d_in[1];
    const void*  side  = d_in[2];
    const float* ft_w  = (const float*)d_in[3];
    const float* ft_b  = (const float*)d_in[4];
    const float* l1_w  = (const float*)d_in[5];
    const float* l1_b  = (const float*)d_in[6];
    const float* l2_w  = (const float*)d_in[7];
    const float* l2_b  = (const float*)d_in[8];
    const float* l3_w  = (const float*)d_in[9];
    const float* l3_b  = (const float*)d_in[10];
    float* out = (float*)d_out;

    const int fused_smem = 16640 + 32768 + 2112 + 4096 + 512;   // 56128 B
    cudaFuncSetAttribute(nnue_fused_kernel,
                         cudaFuncAttributeMaxDynamicSharedMemorySize,
                         fused_smem);

    prep_kernel<<<1, 256>>>((const unsigned char*)side, l1_w, l2_w);
    transpose_ft_kernel<<<dim3(N_IN / 32, H0 / 32), dim3(32, 32)>>>(ft_w);
    nnue_fused_kernel<<<BATCH / RPB, 512, fused_smem>>>(
        white, black, side, ft_b, l1_b, l2_b, l3_w, l3_b, out);
}

// round 9
// speedup vs baseline: 1.5014x; 1.0415x over previous
#include <cuda_runtime.h>
#include <cuda_bf16.h>
#include <cuda_fp16.h>
#include <math.h>

#define N_IN   12288
#define H0     256
#define BATCH  8192
#define RPB    16                 // rows per fused block (one per warp)
#define O0_STRIDE 520             // halves per smem o0 row

// Scratch (static device allocations are allowed)
__device__ __half g_ft_wt_h[N_IN * H0];   // (12288, 256) transposed, fp16
__device__ uint2  g_w1bf[4096];           // w1 B-fragments [(kc*4+nt)*32+lane]
__device__ float  g_w2t[32 * 32];         // l2_w transposed [i][h2]
__device__ int    g_side_mode;            // 0=uint8, 1=int32, 2=float32

__device__ __forceinline__ unsigned smem_u32(const void* p) {
    unsigned a;
    asm("{ .reg .u64 t; cvta.to.shared.u64 t, %1; cvt.u32.u64 %0, t; }"
        : "=r"(a) : "l"(p));
    return a;
}

// ---------------------------------------------------------------------------
// Parallel prep, grid = 16 blocks x 256 threads.
//  - blocks 0..15: each builds 256 of the 4096 w1 B-fragments + 64 w2 entries
//  - block 15 additionally runs the side-dtype sniff (8 KB read)
// B frag (m16n8k16 col-major B): lane holds
//   .x = half2(B[k0][n], B[k0+1][n]), .y = half2(B[k0+8][n], B[k0+9][n])
// k0 = kc*16 + (lane%4)*2, n = nt*8 + lane/4; B[k][n] = l1_w[n*512 + k].
// ---------------------------------------------------------------------------
__global__ void prep_kernel(const unsigned char* __restrict__ p,
                            const float* __restrict__ l1w,
                            const float* __restrict__ l2w) {
    int tid = threadIdx.x;
    int blk = blockIdx.x;

    // w1 fragment slice: one entry per thread
    {
        int idx  = blk * 256 + tid;          // 0..4095
        int lane = idx & 31;
        int t    = idx >> 5;
        int nt   = t & 3;
        int kc   = t >> 2;
        int k0   = kc * 16 + (lane & 3) * 2;
        int n    = nt * 8 + (lane >> 2);
        __half2 x = __floats2half2_rn(l1w[n * 512 + k0],     l1w[n * 512 + k0 + 1]);
        __half2 y = __floats2half2_rn(l1w[n * 512 + k0 + 8], l1w[n * 512 + k0 + 9]);
        uint2 v;
        v.x = *(unsigned*)&x;
        v.y = *(unsigned*)&y;
        g_w1bf[idx] = v;
    }
    // w2 transpose slice: 64 entries per block
    {
        int idx = blk * 64 + (tid & 63);
        if (tid < 64) {
            int h2 = idx >> 5, i = idx & 31;
            g_w2t[i * 32 + h2] = l2w[h2 * 32 + i];
        }
    }
    // side sniff: block 15 only
    if (blk == 15) {
        __shared__ int c3F, cOdd;
        if (tid == 0) { c3F = 0; cOdd = 0; }
        __syncthreads();
        int l3f = 0, lodd = 0;
        for (int i = tid; i < 8192; i += 256) {
            unsigned char b = p[i];
            if ((i & 3) == 3 && b == 0x3F) l3f++;
            if ((i & 3) != 0 && b != 0)    lodd++;
        }
        atomicAdd(&c3F, l3f);
        atomicAdd(&cOdd, lodd);
        __syncthreads();
        if (tid == 0)
            g_side_mode = (c3F > 0) ? 2 : ((cOdd > 0) ? 0 : 1);
    }
}

// ---------------------------------------------------------------------------
// Tiled transpose + fp16 convert: ft_w (256, 12288) -> g_ft_wt_h (12288, 256)
// ---------------------------------------------------------------------------
__global__ void transpose_ft_kernel(const float* __restrict__ ft_w) {
    __shared__ float tile[32][33];
    int f = blockIdx.x * 32 + threadIdx.x;
    int h = blockIdx.y * 32 + threadIdx.y;
    tile[threadIdx.y][threadIdx.x] = ft_w[h * N_IN + f];
    __syncthreads();
    int oh = blockIdx.y * 32 + threadIdx.x;
    int of = blockIdx.x * 32 + threadIdx.y;
    g_ft_wt_h[of * H0 + oh] = __float2half_rn(tile[threadIdx.x][threadIdx.y]);
}

// ---------------------------------------------------------------------------
// Sparse gather-accumulate (scan): fp16 columns, fp32 accumulation.
// h mapping: acc[j] <-> h = lane*8 + j
// ---------------------------------------------------------------------------
__device__ __forceinline__ void accum_mask(unsigned mask, int fbase, int lane,
                                           float acc[8]) {
    while (mask) {
        int b = __ffs(mask) - 1;
        mask &= mask - 1;
        int f = fbase + b * 4;
        const uint4* wp = (const uint4*)(g_ft_wt_h + (size_t)f * H0);
        uint4 a = __ldg(wp + lane);
        const __half2* hp = (const __half2*)&a;
        float2 f0 = __half22float2(hp[0]);
        float2 f1 = __half22float2(hp[1]);
        float2 f2 = __half22float2(hp[2]);
        float2 f3 = __half22float2(hp[3]);
        acc[0] += f0.x; acc[1] += f0.y;
        acc[2] += f1.x; acc[3] += f1.y;
        acc[4] += f2.x; acc[5] += f2.y;
        acc[6] += f3.x; acc[7] += f3.y;
    }
}

__device__ __forceinline__ void process_chunk(const float4 v[4], int base,
                                              int lane, float acc[8]) {
    #pragma unroll
    for (int c = 0; c < 4; c++) {
        int cb = base + c * 128;
        float s = v[c].x + v[c].y + v[c].z + v[c].w;
        unsigned any = __ballot_sync(0xffffffffu, s != 0.0f);
        if (any) {
            unsigned mx = __ballot_sync(0xffffffffu, v[c].x != 0.0f);
            unsigned my = __ballot_sync(0xffffffffu, v[c].y != 0.0f);
            unsigned mz = __ballot_sync(0xffffffffu, v[c].z != 0.0f);
            unsigned mw = __ballot_sync(0xffffffffu, v[c].w != 0.0f);
            accum_mask(mx, cb + 0, lane, acc);
            accum_mask(my, cb + 1, lane, acc);
            accum_mask(mz, cb + 2, lane, acc);
            accum_mask(mw, cb + 3, lane, acc);
        }
    }
}

// ---------------------------------------------------------------------------
// Fused kernel: 16 warps scan 16 rows -> smem o0 -> tensor-core tail.
// smem: o0 (16*520 f16) | bfr (4096 uint2) | o1 (16*33 f32) | w2 | biases
// ---------------------------------------------------------------------------
__global__ __launch_bounds__(512, 2) void nnue_fused_kernel(
    const float* __restrict__ white, const float* __restrict__ black,
    const void* __restrict__ side, const float* __restrict__ ft_b,
    const float* __restrict__ l1_b, const float* __restrict__ l2_b,
    const float* __restrict__ l3_w, const float* __restrict__ l3_b,
    float* __restrict__ out)
{
    extern __shared__ char smraw[];
    __half* o0s = (__half*)smraw;                          // 16*520*2 = 16640B
    uint2*  bfr = (uint2*)(smraw + 16640);                 // 32768B
    float*  o1s = (float*)(smraw + 16640 + 32768);         // 16*33*4 = 2112B
    float*  w2s = (float*)(smraw + 16640 + 32768 + 2112);  // 4096B
    float*  bia = (float*)(smraw + 16640 + 32768 + 2112 + 4096); // 97 floats

    int tid  = threadIdx.x;
    int lane = tid & 31;
    int wid  = tid >> 5;

    // Stage tail constants (cheap, L2-hot)
    {
        const uint4* bs = (const uint4*)g_w1bf;   // 2048 uint4
        uint4* bd = (uint4*)bfr;
        for (int i = tid; i < 2048; i += 512) bd[i] = __ldg(bs + i);
        for (int i = tid; i < 1024; i += 512) w2s[i] = g_w2t[i];
        if (tid < 32) {
            bia[tid]      = l1_b[tid];
            bia[32 + tid] = l2_b[tid];
            bia[64 + tid] = l3_w[tid];
        }
        if (tid == 0) bia[96] = l3_b[0];
    }

    // ---- Scan: warp wid handles row r
    int r = blockIdx.x * RPB + wid;

    float4 b0 = __ldg((const float4*)ft_b + lane * 2);
    float4 b1 = __ldg((const float4*)ft_b + lane * 2 + 1);
    float aw[8] = {b0.x, b0.y, b0.z, b0.w, b1.x, b1.y, b1.z, b1.w};
    float ab[8] = {b0.x, b0.y, b0.z, b0.w, b1.x, b1.y, b1.z, b1.w};

    const float4* wrow = (const float4*)(white + (size_t)r * N_IN);
    const float4* brow = (const float4*)(black + (size_t)r * N_IN);

    for (int base = 0; base < N_IN; base += 512) {
        int q = (base >> 2) + lane;
        float4 wv[4], bv[4];
        #pragma unroll
        for (int c = 0; c < 4; c++) wv[c] = __ldcs(wrow + q + c * 32);
        #pragma unroll
        for (int c = 0; c < 4; c++) bv[c] = __ldcs(brow + q + c * 32);
        process_chunk(wv, base, lane, aw);
        process_chunk(bv, base, lane, ab);
    }

    int mode = g_side_mode;
    bool s;
    if (mode == 0)      s = ((const unsigned char*)side)[r] != 0;
    else if (mode == 1) s = ((const int*)side)[r] != 0;
    else                s = ((const float*)side)[r] != 0.0f;

    float us[8], th[8];
    #pragma unroll
    for (int j = 0; j < 8; j++) {
        float u = s ? aw[j] : ab[j];
        float t = s ? ab[j] : aw[j];
        us[j] = fminf(fmaxf(u, 0.0f), 1.0f);
        th[j] = fminf(fmaxf(t, 0.0f), 1.0f);
    }
    // write o0 row (fp16) to smem: halves [lane*8 .. +8) and [256+lane*8 ..)
    {
        __half2 u0 = __floats2half2_rn(us[0], us[1]);
        __half2 u1 = __floats2half2_rn(us[2], us[3]);
        __half2 u2 = __floats2half2_rn(us[4], us[5]);
        __half2 u3 = __floats2half2_rn(us[6], us[7]);
        __half2 t0 = __floats2half2_rn(th[0], th[1]);
        __half2 t1 = __floats2half2_rn(th[2], th[3]);
        __half2 t2 = __floats2half2_rn(th[4], th[5]);
        __half2 t3 = __floats2half2_rn(th[6], th[7]);
        uint4 pu, pt;
        pu.x = *(unsigned*)&u0; pu.y = *(unsigned*)&u1;
        pu.z = *(unsigned*)&u2; pu.w = *(unsigned*)&u3;
        pt.x = *(unsigned*)&t0; pt.y = *(unsigned*)&t1;
        pt.z = *(unsigned*)&t2; pt.w = *(unsigned*)&t3;
        uint4* orow = (uint4*)(o0s + wid * O0_STRIDE);   // 65 uint4 per row
        orow[lane]      = pu;
        orow[32 + lane] = pt;
    }
    __syncthreads();

    // ---- L1 via tensor cores: warps 0-3, warp nt owns n-tile nt (cols nt*8..+7)
    if (wid < 4) {
        int nt = wid;
        int arow = (lane & 7) + ((lane >> 3) & 1) * 8;
        int akof = ((lane >> 4) & 1) * 8;
        unsigned abase = smem_u32(o0s) + (arow * O0_STRIDE + akof) * 2;

        float c[4] = {0.f, 0.f, 0.f, 0.f};
        #pragma unroll 4
        for (int kc = 0; kc < 32; kc++) {
            unsigned a0, a1, a2, a3;
            asm volatile(
                "ldmatrix.sync.aligned.m8n8.x4.shared.b16 {%0,%1,%2,%3}, [%4];"
                : "=r"(a0), "=r"(a1), "=r"(a2), "=r"(a3)
                : "r"(abase + kc * 32));
            uint2 bB = bfr[(kc * 4 + nt) * 32 + lane];
            asm volatile(
                "mma.sync.aligned.m16n8k16.row.col.f32.f16.f16.f32 "
                "{%0,%1,%2,%3}, {%4,%5,%6,%7}, {%8,%9}, {%0,%1,%2,%3};"
                : "+f"(c[0]), "+f"(c[1]), "+f"(c[2]), "+f"(c[3])
                : "r"(a0), "r"(a1), "r"(a2), "r"(a3), "r"(bB.x), "r"(bB.y));
        }
        // epilogue: bias + clip -> o1s
        int rloc = lane >> 2;
        int col  = nt * 8 + (lane & 3) * 2;
        float bc0 = bia[col], bc1 = bia[col + 1];
        o1s[rloc * 33 + col]           = fminf(fmaxf(c[0] + bc0, 0.f), 1.f);
        o1s[rloc * 33 + col + 1]       = fminf(fmaxf(c[1] + bc1, 0.f), 1.f);
        o1s[(rloc + 8) * 33 + col]     = fminf(fmaxf(c[2] + bc0, 0.f), 1.f);
        o1s[(rloc + 8) * 33 + col + 1] = fminf(fmaxf(c[3] + bc1, 0.f), 1.f);
    }
    __syncthreads();

    // ---- L2/L3: warps 0-1, warp w rows w*8..w*8+7, lane = h2
    if (wid < 2) {
        float acc2[8];
        float bias2 = bia[32 + lane];
        #pragma unroll
        for (int k = 0; k < 8; k++) acc2[k] = bias2;
        #pragma unroll 4
        for (int hh = 0; hh < 32; hh++) {
            float wv = w2s[hh * 32 + lane];
            #pragma unroll
            for (int k = 0; k < 8; k++)
                acc2[k] = fmaf(o1s[(wid * 8 + k) * 33 + hh], wv, acc2[k]);
        }
        float lw = bia[64 + lane];
        float p[8];
        #pragma unroll
        for (int k = 0; k < 8; k++)
            p[k] = fminf(fmaxf(acc2[k], 0.f), 1.f) * lw;
        #pragma unroll
        for (int off = 16; off; off >>= 1) {
            #pragma unroll
            for (int k = 0; k < 8; k++)
                p[k] += __shfl_xor_sync(0xffffffffu, p[k], off);
        }
        if (lane < 8) {
            float t = (p[lane] + bia[96]) * 1.5f;   // OUTPUT_SCALE / WDL_SCALE
            out[blockIdx.x * RPB + wid * 8 + lane] = 1.0f / (1.0f + expf(-t));
        }
    }
}

// ---------------------------------------------------------------------------
extern "C" void kernel_launch(void* const* d_in, const int* in_sizes, int n_in,
                              void* d_out, int out_size) {
    const float* white = (const float*)d_in[0];
    const float* black = (const float*)d_in[1];
    const void*  side  = d_in[2];
    const float* ft_w  = (const float*)d_in[3];
    const float* ft_b  = (const float*)d_in[4];
    const float* l1_w  = (const float*)d_in[5];
    const float* l1_b  = (const float*)d_in[6];
    const float* l2_w  = (const float*)d_in[7];
    const float* l2_b  = (const float*)d_in[8];
    const float* l3_w  = (const float*)d_in[9];
    const float* l3_b  = (const float*)d_in[10];
    float* out = (float*)d_out;

    const int fused_smem = 16640 + 32768 + 2112 + 4096 + 512;   // 56128 B
    cudaFuncSetAttribute(nnue_fused_kernel,
                         cudaFuncAttributeMaxDynamicSharedMemorySize,
                         fused_smem);

    prep_kernel<<<16, 256>>>((const unsigned char*)side, l1_w, l2_w);
    transpose_ft_kernel<<<dim3(N_IN / 32, H0 / 32), dim3(32, 32)>>>(ft_w);
    nnue_fused_kernel<<<BATCH / RPB, 512, fused_smem>>>(
        white, black, side, ft_b, l1_b, l2_b, l3_w, l3_b, out);
}